// round 11
// baseline (speedup 1.0000x reference)
#include <cuda_runtime.h>

// Rotated-BEV IoU loss — ONE kernel, (row-group × gt-segment) blocks,
// register-only clip, last-block reduction.
// d_in[0] iou_pred (N,1) f32, d_in[1] box_pred (N,7) f32,
// d_in[2] box_gt (M,7) f32, d_in[3] num_total_pos (int32 scalar, optional)
// d_out: scalar f32

#define EPSF 1e-8f
#define MAXN 8192
#define MAXSEG 8
#define ROWS_PB 8
#define GTILE 256
#define BLOCK 256

__device__ float g_part[MAXSEG * MAXN];  // per-(segment,row) partial max IoU
__device__ int   g_done = 0;             // last-block counter (reset by reducer)

// ---------------------------------------------------------------------------
// Sum of cross(P,Q) over edges of polygon P (4 verts, CCW) clipped to the
// inside of polygon Q (4 verts, CCW). Fully register-resident, branch-free.
// STRICT=true uses half-open boundary for exactly-collinear edges (B pass).
template <bool STRICT>
__device__ __forceinline__ float clip_edges_sum(
    const float* __restrict__ Px, const float* __restrict__ Py,
    const float* __restrict__ Qx, const float* __restrict__ Qy)
{
    float tot = 0.0f;
#pragma unroll
    for (int i = 0; i < 4; ++i) {
        const float p1x = Px[i], p1y = Py[i];
        const float dax = Px[(i + 1) & 3] - p1x;
        const float day = Py[(i + 1) & 3] - p1y;
        float t0 = 0.0f, t1 = 1.0f;
#pragma unroll
        for (int j = 0; j < 4; ++j) {
            const float qx = Qx[j], qy = Qy[j];
            const float dbx = Qx[(j + 1) & 3] - qx;
            const float dby = Qy[(j + 1) & 3] - qy;
            // constraint: c0 + t*c1 >= 0  (inside = left of Q edge)
            const float c1 = dbx * day - dby * dax;
            const float c0 = dbx * (p1y - qy) - dby * (p1x - qx);
            const float tc = __fdividef(-c0, c1);
            if (c1 > 0.0f)      t0 = fmaxf(t0, tc);
            else if (c1 < 0.0f) t1 = fminf(t1, tc);
            else if (STRICT ? (c0 <= 0.0f) : (c0 < 0.0f)) t1 = -1.0f;
        }
        if (t1 > t0) {
            const float sx = fmaf(t0, dax, p1x), sy = fmaf(t0, day, p1y);
            const float ex = fmaf(t1, dax, p1x), ey = fmaf(t1, day, p1y);
            tot += sx * ey - sy * ex;
        }
    }
    return tot;
}

// ---------------------------------------------------------------------------
__global__ void __launch_bounds__(BLOCK)
fused_kernel(const float* __restrict__ iou_pred,
             const float* __restrict__ box_pred,
             const float* __restrict__ box_gt,
             float* __restrict__ out,
             const int* __restrict__ ntp_ptr, int has_ntp,
             int N, int M, int nseg)
{
    // gt tile
    __shared__ float sgx[GTILE], sgy[GTILE], sgex[GTILE], sgey[GTILE];
    __shared__ float sghx[GTILE], sghy[GTILE], sgc[GTILE], sgs[GTILE];
    // pred rows (block-exclusive within this segment)
    __shared__ float prx[ROWS_PB], pry[ROWS_PB], prex[ROWS_PB], prey[ROWS_PB];
    __shared__ float parea[ROWS_PB];
    __shared__ float pcx[ROWS_PB][4], pcy[ROWS_PB][4];
    __shared__ int   rowmaxbits[ROWS_PB];
    __shared__ int   scnt;
    __shared__ int   slist[ROWS_PB * GTILE];

    const int tid = threadIdx.x;
    const int lane = tid & 31;
    const int seg = blockIdx.x % nseg;
    const int rowgrp = blockIdx.x / nseg;
    const int row0 = rowgrp * ROWS_PB;
    const int nrows = min(ROWS_PB, N - row0);

    // ---- pred-row prep ----
    if (tid < ROWS_PB) {
        rowmaxbits[tid] = 0;
        const int row = row0 + tid;
        if (row < N) {
            const float* b = box_pred + (size_t)row * 7;
            const float x = b[0], y = b[1];
            const float hx = 0.5f * b[3], hy = 0.5f * b[4];
            float s, c;
            __sincosf(b[6], &s, &c);
            prx[tid] = x; pry[tid] = y;
            prex[tid] = hx * fabsf(c) + hy * fabsf(s) + 1e-4f;
            prey[tid] = hx * fabsf(s) + hy * fabsf(c) + 1e-4f;
            parea[tid] = b[3] * b[4];
            pcx[tid][0] = x + c * hx - s * hy;  pcy[tid][0] = y + s * hx + c * hy;
            pcx[tid][1] = x - c * hx - s * hy;  pcy[tid][1] = y - s * hx + c * hy;
            pcx[tid][2] = x - c * hx + s * hy;  pcy[tid][2] = y - s * hx - c * hy;
            pcx[tid][3] = x + c * hx + s * hy;  pcy[tid][3] = y + s * hx - c * hy;
        }
    }
    if (tid == 0) scnt = 0;

    // ---- this segment's gt tiles: jt = seg*GTILE, step nseg*GTILE ----
    for (int jt = seg * GTILE; jt < M; jt += nseg * GTILE) {
        const int csz = min(GTILE, M - jt);
        __syncthreads();
        if (tid < csz) {
            const float* b = box_gt + (size_t)(jt + tid) * 7;
            const float x = b[0], y = b[1];
            const float hx = 0.5f * b[3], hy = 0.5f * b[4];
            float s, c;
            __sincosf(b[6], &s, &c);
            sgx[tid] = x; sgy[tid] = y;
            sgex[tid] = hx * fabsf(c) + hy * fabsf(s) + 1e-4f;
            sgey[tid] = hx * fabsf(s) + hy * fabsf(c) + 1e-4f;
            sghx[tid] = hx; sghy[tid] = hy; sgc[tid] = c; sgs[tid] = s;
        }
        __syncthreads();

        // AABB test: ROWS_PB rows x csz gt (single trip: GTILE == BLOCK)
        {
            const int j = tid;
            const bool jvalid = (j < csz);
            float gxv = 0.f, gyv = 0.f, gexv = -1e30f, geyv = -1e30f;
            if (jvalid) { gxv = sgx[j]; gyv = sgy[j]; gexv = sgex[j]; geyv = sgey[j]; }
            for (int r = 0; r < nrows; ++r) {
                const bool pass = jvalid &
                    (fabsf(prx[r] - gxv) <= prex[r] + gexv) &
                    (fabsf(pry[r] - gyv) <= prey[r] + geyv);
                const unsigned msk = __ballot_sync(0xFFFFFFFFu, pass);
                if (msk) {
                    const int leader = __ffs(msk) - 1;
                    int base = 0;
                    if (lane == leader) base = atomicAdd(&scnt, __popc(msk));
                    base = __shfl_sync(0xFFFFFFFFu, base, leader);
                    if (pass)
                        slist[base + __popc(msk & ((1u << lane) - 1u))] = (r << 16) | j;
                }
            }
        }
        __syncthreads();

        // clip survivors (register-only, branch-free math)
        const int cnt = scnt;
        for (int i = tid; i < cnt; i += BLOCK) {
            const int pk = slist[i];
            const int r = pk >> 16;
            const int jj = pk & 0xFFFF;
            float Ax[4], Ay[4], Bx[4], By[4];
#pragma unroll
            for (int k = 0; k < 4; ++k) { Ax[k] = pcx[r][k]; Ay[k] = pcy[r][k]; }
            const float x = sgx[jj], y = sgy[jj];
            const float hx = sghx[jj], hy = sghy[jj];
            const float c = sgc[jj], s = sgs[jj];
            Bx[0] = x + c * hx - s * hy;  By[0] = y + s * hx + c * hy;
            Bx[1] = x - c * hx - s * hy;  By[1] = y - s * hx + c * hy;
            Bx[2] = x - c * hx + s * hy;  By[2] = y - s * hx - c * hy;
            Bx[3] = x + c * hx + s * hy;  By[3] = y + s * hx - c * hy;

            const float twoA = clip_edges_sum<false>(Ax, Ay, Bx, By)
                             + clip_edges_sum<true >(Bx, By, Ax, Ay);
            const float inter = 0.5f * fmaxf(twoA, 0.0f);
            if (inter > 0.0f) {
                const float uni = fmaxf(parea[r] + 4.0f * hx * hy - inter, EPSF);
                atomicMax(&rowmaxbits[r], __float_as_int(inter / uni));
            }
        }
        __syncthreads();
        if (tid == 0) scnt = 0;
    }
    __syncthreads();

    // write this (segment, row-group) partial max — block-exclusive slot
    if (tid < nrows)
        g_part[seg * MAXN + row0 + tid] = __int_as_float(rowmaxbits[tid]);

    // ---- last finished block does the deterministic final reduction ----
    __shared__ int isLast;
    if (tid == 0) {
        __threadfence();
        isLast = (atomicAdd(&g_done, 1) == (int)gridDim.x - 1);
    }
    __syncthreads();
    if (!isLast) return;
    __threadfence();

    float sum = 0.0f;
    for (int i = tid; i < N; i += BLOCK) {
        float mx = g_part[i];
        for (int s2 = 1; s2 < nseg; ++s2)
            mx = fmaxf(mx, g_part[s2 * MAXN + i]);
        sum += fabsf(iou_pred[i] - (2.0f * mx - 1.0f));
    }
#pragma unroll
    for (int o = 16; o > 0; o >>= 1)
        sum += __shfl_down_sync(0xFFFFFFFFu, sum, o);

    __shared__ float wsum[BLOCK / 32];
    if (lane == 0) wsum[tid >> 5] = sum;
    __syncthreads();
    if (tid == 0) {
        float tot = 0.0f;
#pragma unroll
        for (int w = 0; w < BLOCK / 32; ++w) tot += wsum[w];
        float ntp = 2048.0f;
        if (has_ntp) {
            const int iv = *ntp_ptr;
            if (iv > 0 && iv < 100000000) ntp = (float)iv;
            else ntp = __int_as_float(iv);
        }
        out[0] = tot / (ntp + 1e-4f);
        g_done = 0;   // reset for next graph replay
    }
}

// ---------------------------------------------------------------------------
extern "C" void kernel_launch(void* const* d_in, const int* in_sizes, int n_in,
                              void* d_out, int out_size)
{
    const float* iou_pred = (const float*)d_in[0];
    const float* box_pred = (const float*)d_in[1];
    const float* box_gt   = (const float*)d_in[2];
    const int N = in_sizes[1] / 7;
    const int M = in_sizes[2] / 7;
    const int* ntp_ptr = (n_in >= 4) ? (const int*)d_in[3] : nullptr;
    const int has_ntp = (n_in >= 4) ? 1 : 0;

    int nseg = (M + GTILE - 1) / GTILE;
    if (nseg > MAXSEG) nseg = MAXSEG;
    const int nrowgrps = (N + ROWS_PB - 1) / ROWS_PB;
    fused_kernel<<<nrowgrps * nseg, BLOCK>>>(iou_pred, box_pred, box_gt,
                                             (float*)d_out, ntp_ptr, has_ntp,
                                             N, M, nseg);
}

// round 13
// speedup vs baseline: 1.6228x; 1.6228x over previous
#include <cuda_runtime.h>

// Rotated-BEV IoU loss — ONE kernel, one block per SM (single wave),
// 16 rows/block, 512 threads, register-only clip, last-block reduction.

#define EPSF 1e-8f
#define MAXN 8192
#define ROWS_PB 16
#define GTILE 512
#define BLOCK 512

__device__ float g_row[MAXN];   // per-row |iou_pred - target|
__device__ int   g_done = 0;    // last-block counter (reset by reducer)

// ---------------------------------------------------------------------------
// Sum of cross(P,Q) over edges of polygon P (4 verts, CCW) clipped to the
// inside of polygon Q (4 verts, CCW). Register-resident, branch-free.
// STRICT=true uses half-open boundary for exactly-collinear edges (B pass).
template <bool STRICT>
__device__ __forceinline__ float clip_edges_sum(
    const float* __restrict__ Px, const float* __restrict__ Py,
    const float* __restrict__ Qx, const float* __restrict__ Qy)
{
    float tot = 0.0f;
#pragma unroll
    for (int i = 0; i < 4; ++i) {
        const float p1x = Px[i], p1y = Py[i];
        const float dax = Px[(i + 1) & 3] - p1x;
        const float day = Py[(i + 1) & 3] - p1y;
        float t0 = 0.0f, t1 = 1.0f;
#pragma unroll
        for (int j = 0; j < 4; ++j) {
            const float qx = Qx[j], qy = Qy[j];
            const float dbx = Qx[(j + 1) & 3] - qx;
            const float dby = Qy[(j + 1) & 3] - qy;
            // constraint: c0 + t*c1 >= 0  (inside = left of Q edge)
            const float c1 = dbx * day - dby * dax;
            const float c0 = dbx * (p1y - qy) - dby * (p1x - qx);
            const float tc = __fdividef(-c0, c1);
            if (c1 > 0.0f)      t0 = fmaxf(t0, tc);
            else if (c1 < 0.0f) t1 = fminf(t1, tc);
            else if (STRICT ? (c0 <= 0.0f) : (c0 < 0.0f)) t1 = -1.0f;
        }
        if (t1 > t0) {
            const float sx = fmaf(t0, dax, p1x), sy = fmaf(t0, day, p1y);
            const float ex = fmaf(t1, dax, p1x), ey = fmaf(t1, day, p1y);
            tot += sx * ey - sy * ex;
        }
    }
    return tot;
}

// ---------------------------------------------------------------------------
__global__ void __launch_bounds__(BLOCK)
fused_kernel(const float* __restrict__ iou_pred,
             const float* __restrict__ box_pred,
             const float* __restrict__ box_gt,
             float* __restrict__ out,
             const int* __restrict__ ntp_ptr, int has_ntp,
             int N, int M)
{
    // gt tile (8 * 512 * 4 = 16 KB)
    __shared__ float sgx[GTILE], sgy[GTILE], sgex[GTILE], sgey[GTILE];
    __shared__ float sghx[GTILE], sghy[GTILE], sgc[GTILE], sgs[GTILE];
    // pred rows (block-exclusive)
    __shared__ float prx[ROWS_PB], pry[ROWS_PB], prex[ROWS_PB], prey[ROWS_PB];
    __shared__ float parea[ROWS_PB];
    __shared__ float pcx[ROWS_PB][4], pcy[ROWS_PB][4];
    __shared__ int   rowmaxbits[ROWS_PB];
    __shared__ int   scnt;
    // packed survivors: (r << 9) | j  with r < 16, j < 512  (16 KB)
    __shared__ unsigned short slist[ROWS_PB * GTILE];

    const int tid = threadIdx.x;
    const int lane = tid & 31;
    const int row0 = blockIdx.x * ROWS_PB;
    const int nrows = min(ROWS_PB, N - row0);

    // ---- pred-row prep ----
    if (tid < ROWS_PB) {
        rowmaxbits[tid] = 0;
        const int row = row0 + tid;
        if (row < N) {
            const float* b = box_pred + (size_t)row * 7;
            const float x = b[0], y = b[1];
            const float hx = 0.5f * b[3], hy = 0.5f * b[4];
            float s, c;
            __sincosf(b[6], &s, &c);
            prx[tid] = x; pry[tid] = y;
            prex[tid] = hx * fabsf(c) + hy * fabsf(s) + 1e-4f;
            prey[tid] = hx * fabsf(s) + hy * fabsf(c) + 1e-4f;
            parea[tid] = b[3] * b[4];
            pcx[tid][0] = x + c * hx - s * hy;  pcy[tid][0] = y + s * hx + c * hy;
            pcx[tid][1] = x - c * hx - s * hy;  pcy[tid][1] = y - s * hx + c * hy;
            pcx[tid][2] = x - c * hx + s * hy;  pcy[tid][2] = y - s * hx - c * hy;
            pcx[tid][3] = x + c * hx + s * hy;  pcy[tid][3] = y + s * hx - c * hy;
        }
    }
    if (tid == 0) scnt = 0;

    // ---- tiles over gt boxes (single tile when M <= GTILE) ----
    for (int jt = 0; jt < M; jt += GTILE) {
        const int csz = min(GTILE, M - jt);
        __syncthreads();
        if (tid < csz) {
            const float* b = box_gt + (size_t)(jt + tid) * 7;
            const float x = b[0], y = b[1];
            const float hx = 0.5f * b[3], hy = 0.5f * b[4];
            float s, c;
            __sincosf(b[6], &s, &c);
            sgx[tid] = x; sgy[tid] = y;
            sgex[tid] = hx * fabsf(c) + hy * fabsf(s) + 1e-4f;
            sgey[tid] = hx * fabsf(s) + hy * fabsf(c) + 1e-4f;
            sghx[tid] = hx; sghy[tid] = hy; sgc[tid] = c; sgs[tid] = s;
        }
        __syncthreads();

        // AABB test: ROWS_PB rows x csz gt (single trip: GTILE == BLOCK)
        {
            const int j = tid;
            const bool jvalid = (j < csz);
            float gxv = 0.f, gyv = 0.f, gexv = -1e30f, geyv = -1e30f;
            if (jvalid) { gxv = sgx[j]; gyv = sgy[j]; gexv = sgex[j]; geyv = sgey[j]; }
            for (int r = 0; r < nrows; ++r) {
                const bool pass = jvalid &
                    (fabsf(prx[r] - gxv) <= prex[r] + gexv) &
                    (fabsf(pry[r] - gyv) <= prey[r] + geyv);
                const unsigned msk = __ballot_sync(0xFFFFFFFFu, pass);
                if (msk) {
                    const int leader = __ffs(msk) - 1;
                    int base = 0;
                    if (lane == leader) base = atomicAdd(&scnt, __popc(msk));
                    base = __shfl_sync(0xFFFFFFFFu, base, leader);
                    if (pass)
                        slist[base + __popc(msk & ((1u << lane) - 1u))] =
                            (unsigned short)((r << 9) | j);
                }
            }
        }
        __syncthreads();

        // clip survivors (register-only, branch-free math)
        const int cnt = scnt;
        for (int i = tid; i < cnt; i += BLOCK) {
            const int pk = slist[i];
            const int r = pk >> 9;
            const int jj = pk & 0x1FF;
            float Ax[4], Ay[4], Bx[4], By[4];
#pragma unroll
            for (int k = 0; k < 4; ++k) { Ax[k] = pcx[r][k]; Ay[k] = pcy[r][k]; }
            const float x = sgx[jj], y = sgy[jj];
            const float hx = sghx[jj], hy = sghy[jj];
            const float c = sgc[jj], s = sgs[jj];
            Bx[0] = x + c * hx - s * hy;  By[0] = y + s * hx + c * hy;
            Bx[1] = x - c * hx - s * hy;  By[1] = y - s * hx + c * hy;
            Bx[2] = x - c * hx + s * hy;  By[2] = y - s * hx - c * hy;
            Bx[3] = x + c * hx + s * hy;  By[3] = y + s * hx - c * hy;

            const float twoA = clip_edges_sum<false>(Ax, Ay, Bx, By)
                             + clip_edges_sum<true >(Bx, By, Ax, Ay);
            const float inter = 0.5f * fmaxf(twoA, 0.0f);
            if (inter > 0.0f) {
                const float uni = fmaxf(parea[r] + 4.0f * hx * hy - inter, EPSF);
                atomicMax(&rowmaxbits[r], __float_as_int(inter / uni));
            }
        }
        __syncthreads();
        if (tid == 0) scnt = 0;
    }
    __syncthreads();

    if (tid < nrows) {
        const int row = row0 + tid;
        const float mx = __int_as_float(rowmaxbits[tid]);
        g_row[row] = fabsf(iou_pred[row] - (2.0f * mx - 1.0f));
    }

    // ---- last finished block does the deterministic final reduction ----
    __shared__ int isLast;
    if (tid == 0) {
        __threadfence();
        isLast = (atomicAdd(&g_done, 1) == (int)gridDim.x - 1);
    }
    __syncthreads();
    if (!isLast) return;
    __threadfence();

    float sum = 0.0f;
    for (int i = tid; i < N; i += BLOCK) sum += g_row[i];
#pragma unroll
    for (int o = 16; o > 0; o >>= 1)
        sum += __shfl_down_sync(0xFFFFFFFFu, sum, o);

    __shared__ float wsum[BLOCK / 32];
    if (lane == 0) wsum[tid >> 5] = sum;
    __syncthreads();
    if (tid == 0) {
        float tot = 0.0f;
#pragma unroll
        for (int w = 0; w < BLOCK / 32; ++w) tot += wsum[w];
        float ntp = 2048.0f;
        if (has_ntp) {
            const int iv = *ntp_ptr;
            if (iv > 0 && iv < 100000000) ntp = (float)iv;
            else ntp = __int_as_float(iv);
        }
        out[0] = tot / (ntp + 1e-4f);
        g_done = 0;   // reset for next graph replay
    }
}

// ---------------------------------------------------------------------------
extern "C" void kernel_launch(void* const* d_in, const int* in_sizes, int n_in,
                              void* d_out, int out_size)
{
    const float* iou_pred = (const float*)d_in[0];
    const float* box_pred = (const float*)d_in[1];
    const float* box_gt   = (const float*)d_in[2];
    const int N = in_sizes[1] / 7;
    const int M = in_sizes[2] / 7;
    const int* ntp_ptr = (n_in >= 4) ? (const int*)d_in[3] : nullptr;
    const int has_ntp = (n_in >= 4) ? 1 : 0;

    const int grid = (N + ROWS_PB - 1) / ROWS_PB;   // 128 blocks for N=2048
    fused_kernel<<<grid, BLOCK>>>(iou_pred, box_pred, box_gt, (float*)d_out,
                                  ntp_ptr, has_ntp, N, M);
}